// round 14
// baseline (speedup 1.0000x reference)
#include <cuda_runtime.h>
#include <cuda_bf16.h>

#define BB 4
#define NN 8192
#define CC 1024
#define SS 16
#define NTOK (BB * NN)       // 32768
#define CHUNK 64
#define NCHB (NN / CHUNK)    // 128 chunks per batch
#define NCHG (BB * NCHB)     // 512 chunks total

typedef unsigned long long ull;

// Decoupled-lookback state
__device__ float g_agg[NCHG][SS];  // per-chunk aggregate (16 states)
__device__ int g_flag[NCHG];       // 0 = not ready, 1 = aggregate ready

// ---------- helpers ----------
__device__ __forceinline__ ull dup2(float x) {
    ull r;
    unsigned u = __float_as_uint(x);
    asm("mov.b64 %0, {%1, %1};" : "=l"(r) : "r"(u));
    return r;
}
__device__ __forceinline__ void fma2(ull& d, ull a, ull b) {
    asm("fma.rn.f32x2 %0, %1, %2, %0;" : "+l"(d) : "l"(a), "l"(b));
}
__device__ __forceinline__ ull add2(ull a, ull b) {
    ull r;
    asm("add.rn.f32x2 %0, %1, %2;" : "=l"(r) : "l"(a), "l"(b));
    return r;
}
__device__ __forceinline__ void unpack2(ull v, float& lo, float& hi) {
    unsigned a, b;
    asm("mov.b64 {%0, %1}, %2;" : "=r"(a), "=r"(b) : "l"(v));
    lo = __uint_as_float(a);
    hi = __uint_as_float(b);
}
__device__ __forceinline__ unsigned sptr(const void* p) {
    unsigned r;
    asm("{.reg .u64 t; cvta.to.shared.u64 t, %1; cvt.u32.u64 %0, t;}"
        : "=r"(r) : "l"(p));
    return r;
}
__device__ __forceinline__ void cp16(unsigned d, const void* s) {
    asm volatile("cp.async.ca.shared.global [%0], [%1], 16;" :: "r"(d), "l"(s));
}
__device__ __forceinline__ void cp_commit() {
    asm volatile("cp.async.commit_group;");
}

// ---------- smem carve ----------
#define XSROW 68
#define OFF_XS 0                         // 2 x 64 x 68 floats = 34816 B
#define OFF_AS 34816                     // 2 x 512 ull       = 8192 B
#define OFF_RAW 43008                    // 16 x 72 floats    = 4608 B
#define OFF_CS 47616                     // 64 x 18 ull       = 9216 B
#define OFF_CSUM 56832                   // 8 x 2 ull         = 128 B
#define OFF_PART 56960                   // 16 x 17 floats    = 1088 B
#define OFF_PFX 58048                    // 16 floats         = 64 B
#define SMEM_TOTAL 58112

// ================= reset: clear flags =================
__global__ void k_reset() {
    if (threadIdx.x < NCHG) g_flag[threadIdx.x] = 0;
}

// ================= fused SSM kernel =================
// Grid = 512 (one 64-token chunk, full 1024 c). 256 thr = 8 warps.
__global__ void __launch_bounds__(256) k_fused(const float* __restrict__ x,
                                               const float* __restrict__ A,
                                               const float* __restrict__ Dg,
                                               float* __restrict__ out) {
    extern __shared__ char sm[];
    float* xs0 = (float*)(sm + OFF_XS);
    float* xs1 = (float*)(sm + OFF_XS + 64 * XSROW * 4);
    ull* As0 = (ull*)(sm + OFF_AS);
    ull* As1 = (ull*)(sm + OFF_AS + 4096);
    float (*raw_s)[72] = (float(*)[72])(sm + OFF_RAW);   // [state][token]
    ull (*cs_s)[18] = (ull(*)[18])(sm + OFF_CS);         // dup'd cumstate
    ull (*csum_s)[2] = (ull(*)[2])(sm + OFF_CSUM);
    float (*part_s)[17] = (float(*)[17])(sm + OFF_PART);
    float* pfx_s = (float*)(sm + OFF_PFX);

    const int tid = threadIdx.x;
    const int w = tid >> 5;
    const int l = tid & 31;
    const int g = blockIdx.x;          // global chunk
    const int bch = g & (NCHB - 1);    // chunk within batch
    const int base = g & ~(NCHB - 1);  // first chunk of this batch
    const long T0 = (long)g * CHUNK;

    // ---------------- Phase A: x_state for this chunk (full 1024 c) --------
    auto issue = [&](int it, int buf) {
        float* xsb = buf ? xs1 : xs0;
        ull* Asb = buf ? As1 : As0;
        const float* xbase = x + T0 * CC + it * 64;
#pragma unroll
        for (int j = 0; j < 4; j++) {
            int o = tid + j * 256;
            int t = o >> 4, sub = o & 15;
            cp16(sptr(&xsb[t * XSROW + sub * 4]),
                 xbase + (long)t * CC + sub * 4);
        }
        {
            int c = tid >> 2, k = tid & 3;
            cp16(sptr(&Asb[c * 8 + k * 2]), A + (it * 64 + c) * SS + k * 4);
        }
        cp_commit();
    };

    issue(0, 0);
    issue(1, 1);

    ull acc[2][8];
#pragma unroll
    for (int t = 0; t < 2; t++)
#pragma unroll
        for (int jp = 0; jp < 8; jp++) acc[t][jp] = 0ull;

    for (int it = 0; it < 16; it++) {
        const int buf = it & 1;
        if (it < 15)
            asm volatile("cp.async.wait_group 1;");
        else
            asm volatile("cp.async.wait_group 0;");
        __syncthreads();

        const float* xsb = buf ? xs1 : xs0;
        const ull* Asb = buf ? As1 : As0;
        const float* xa = &xsb[l * XSROW + w * 8];
        const float* xb = &xsb[(32 + l) * XSROW + w * 8];
        const ull* Arow = &Asb[w * 8 * 8];

#pragma unroll
        for (int cc = 0; cc < 2; cc++) {
            float4 va = *reinterpret_cast<const float4*>(xa + cc * 4);
            float4 vb = *reinterpret_cast<const float4*>(xb + cc * 4);
            float fa[4] = {va.x, va.y, va.z, va.w};
            float fb[4] = {vb.x, vb.y, vb.z, vb.w};
#pragma unroll
            for (int k = 0; k < 4; k++) {
                const int c = cc * 4 + k;
                ull xda = dup2(fa[k]);
                ull xdb = dup2(fb[k]);
#pragma unroll
                for (int jq = 0; jq < 4; jq++) {
                    ulonglong2 a2 = *reinterpret_cast<const ulonglong2*>(
                        Arow + c * 8 + jq * 2);
                    fma2(acc[0][jq * 2], xda, a2.x);
                    fma2(acc[0][jq * 2 + 1], xda, a2.y);
                    fma2(acc[1][jq * 2], xdb, a2.x);
                    fma2(acc[1][jq * 2 + 1], xdb, a2.y);
                }
            }
        }
        __syncthreads();
        if (it + 2 < 16) issue(it + 2, buf);
    }

    // cross-warp reduce (alias xs region as red[8 e][64 t][8 jp] ull)
    __syncthreads();
    ull* red = (ull*)(sm + OFF_XS);
#pragma unroll
    for (int jp = 0; jp < 8; jp++) {
        red[((w * 64) + l) * 8 + jp] = acc[0][jp];
        red[((w * 64) + 32 + l) * 8 + jp] = acc[1][jp];
    }
    __syncthreads();

    const int jj = tid >> 6;  // 0..3 -> states 4jj..4jj+3
    const int t = tid & 63;
    ull s0 = 0ull, s1 = 0ull;
#pragma unroll
    for (int e = 0; e < 8; e++) {
        ulonglong2 v = *reinterpret_cast<const ulonglong2*>(
            &red[(e * 64 + t) * 8 + jj * 2]);
        s0 = add2(s0, v.x);
        s1 = add2(s1, v.y);
    }
    // stash per-token state (transposed) in smem
    {
        float f0, f1, f2, f3;
        unpack2(s0, f0, f1);
        unpack2(s1, f2, f3);
        raw_s[4 * jj + 0][t] = f0;
        raw_s[4 * jj + 1][t] = f1;
        raw_s[4 * jj + 2][t] = f2;
        raw_s[4 * jj + 3][t] = f3;
    }

    // chunk aggregate over 64 tokens
#pragma unroll
    for (int o = 16; o; o >>= 1) {
        s0 = add2(s0, __shfl_xor_sync(0xffffffffu, s0, o));
        s1 = add2(s1, __shfl_xor_sync(0xffffffffu, s1, o));
    }
    if (l == 0) {
        csum_s[w][0] = s0;
        csum_s[w][1] = s1;
    }
    __syncthreads();
    if (tid < 4) {
        ull v0 = add2(csum_s[2 * tid][0], csum_s[2 * tid + 1][0]);
        ull v1 = add2(csum_s[2 * tid][1], csum_s[2 * tid + 1][1]);
        float f0, f1, f2, f3;
        unpack2(v0, f0, f1);
        unpack2(v1, f2, f3);
        g_agg[g][tid * 4 + 0] = f0;
        g_agg[g][tid * 4 + 1] = f1;
        g_agg[g][tid * 4 + 2] = f2;
        g_agg[g][tid * 4 + 3] = f3;
    }
    __syncthreads();  // all agg writes issued (cta-scope happens-before)
    if (tid == 0) {
        asm volatile("fence.acq_rel.gpu;" ::: "memory");
        asm volatile("st.relaxed.gpu.global.b32 [%0], %1;"
                     :: "l"(&g_flag[g]), "r"(1) : "memory");
    }

    // ---------------- Phase B: A-only windowed lookback --------------------
    if (bch == 0) {
        if (tid < SS) pfx_s[tid] = 0.f;
    } else {
        const int pr = tid >> 4;  // 0..15 predecessor slot
        const int j = tid & 15;   // state
        float accv = 0.f;
        for (int p0 = 0; p0 < bch; p0 += 16) {
            const int pred = p0 + pr;
            if (pred < bch) {
                const int gp = base + pred;
                unsigned f;
                do {
                    asm volatile("ld.acquire.gpu.global.b32 %0, [%1];"
                                 : "=r"(f) : "l"(&g_flag[gp]) : "memory");
                    if (!f) __nanosleep(64);
                } while (!f);
                accv += g_agg[gp][j];
            }
        }
        part_s[pr][j] = accv;
        __syncthreads();
        if (tid < SS) {
            float s = 0.f;
#pragma unroll
            for (int r = 0; r < 16; r++) s += part_s[r][tid];
            pfx_s[tid] = s;
        }
    }
    __syncthreads();

    // ---------------- Phase C: scan + (cumstate @ D) -----------------------
    // warps 0..7: states 2w, 2w+1; lane = token; raw_s reads are smem.
#pragma unroll
    for (int q = 0; q < 2; q++) {
        const int j = w * 2 + q;
        const float pfx = pfx_s[j];
        float v0 = raw_s[j][l];
        float v1 = raw_s[j][32 + l];
#pragma unroll
        for (int o = 1; o < 32; o <<= 1) {
            float u = __shfl_up_sync(0xffffffffu, v0, o);
            if (l >= o) v0 += u;
        }
        const float carry = __shfl_sync(0xffffffffu, v0, 31);
#pragma unroll
        for (int o = 1; o < 32; o <<= 1) {
            float u = __shfl_up_sync(0xffffffffu, v1, o);
            if (l >= o) v1 += u;
        }
        cs_s[l][j] = dup2(v0 + pfx);
        cs_s[32 + l][j] = dup2(v1 + pfx + carry);
    }
    __syncthreads();

    // D fragment: thread owns c = 4*tid .. +3
    const int cbase = tid * 4;
    ulonglong2 dfrag[SS];
#pragma unroll
    for (int j = 0; j < SS; j++)
        dfrag[j] = *reinterpret_cast<const ulonglong2*>(Dg + j * CC + cbase);

    float* op = out + T0 * CC + cbase;
#pragma unroll 2
    for (int tt = 0; tt < CHUNK; tt++) {
        ull o01 = 0ull, o23 = 0ull;
#pragma unroll
        for (int q = 0; q < 8; q++) {
            ulonglong2 cv =
                *reinterpret_cast<const ulonglong2*>(&cs_s[tt][q * 2]);  // bcast
            fma2(o01, cv.x, dfrag[2 * q].x);
            fma2(o23, cv.x, dfrag[2 * q].y);
            fma2(o01, cv.y, dfrag[2 * q + 1].x);
            fma2(o23, cv.y, dfrag[2 * q + 1].y);
        }
        asm volatile("st.global.cs.v2.u64 [%0], {%1, %2};"
                     :: "l"(op + (long)tt * CC), "l"(o01), "l"(o23)
                     : "memory");
    }
}

extern "C" void kernel_launch(void* const* d_in, const int* in_sizes, int n_in,
                              void* d_out, int out_size) {
    const float* x = (const float*)d_in[0];
    const float* A = (const float*)d_in[1];
    const float* D = (const float*)d_in[2];
    float* out = (float*)d_out;

    cudaFuncSetAttribute(k_fused, cudaFuncAttributeMaxDynamicSharedMemorySize,
                         SMEM_TOTAL);

    k_reset<<<1, NCHG>>>();
    k_fused<<<NCHG, 256, SMEM_TOTAL>>>(x, A, D, out);
}